// round 16
// baseline (speedup 1.0000x reference)
#include <cuda_runtime.h>

// out[b,s,f,o] = sum_{t,k,c} x[b, s+t-2, f*(k+1), c] * W[t,k,c,o],  f*(k+1) < F
// x [4,1024,512,4] f32, W [5,4,4,4] f32, out [4,1024,512,4] f32.
//
// R16: R13 (smem tile, LDS gathers, o-pair FFMA2, in-block warp balance,
//      direct-memcpy constant weights) with the k loop replaced by LITERAL-k
//      template stages: all weight addresses become compile-time immediates
//      -> LDCU on the uniform port (floor 1) instead of GPR-dest LDC
//      (floor 8), removing the hidden constant-port serializer.

#define B_  4
#define S_  1024
#define F_  512
#define U_  4
#define NT  5
#define NK  4
#define TPB 256

typedef unsigned long long u64;

// raw layout: WcR[t][k][c] = (W[t][k][c][0..1], W[t][k][c][2..3]) as o-pairs
__constant__ ulonglong2 WcR[NT][NK][4];

__device__ __forceinline__ u64 fma2(u64 a, u64 b, u64 c) {
    u64 d;
    asm("fma.rn.f32x2 %0, %1, %2, %3;" : "=l"(d) : "l"(a), "l"(b), "l"(c));
    return d;
}
__device__ __forceinline__ u64 dup2(float v) {
    u64 d;
    asm("mov.b64 %0, {%1, %1};" : "=l"(d) : "f"(v));
    return d;
}

struct Row { u64 c0, c1, c2, c3; };

__device__ __forceinline__ Row loadRow(const float4* __restrict__ p) {
    float4 v = *p;
    Row r;
    r.c0 = dup2(v.x); r.c1 = dup2(v.y); r.c2 = dup2(v.z); r.c3 = dup2(v.w);
    return r;
}

// one harmonic with LITERAL k: weight addresses are compile-time immediates
template <int K>
__device__ __forceinline__ void harmonic(
    const float4* __restrict__ col, u64 acc[U_][2])
{
    Row w4[4];
#pragma unroll
    for (int m = 0; m < 4; ++m) w4[m] = loadRow(col + m * F_);

#pragma unroll
    for (int t = 0; t < NT; ++t) {
        ulonglong2 q0 = WcR[t][K][0];
        ulonglong2 q1 = WcR[t][K][1];
        ulonglong2 q2 = WcR[t][K][2];
        ulonglong2 q3 = WcR[t][K][3];
#pragma unroll
        for (int j = 0; j < U_; ++j) {
            Row rv = w4[(t + j) & 3];
            acc[j][0] = fma2(rv.c0, q0.x, acc[j][0]);
            acc[j][1] = fma2(rv.c0, q0.y, acc[j][1]);
            acc[j][0] = fma2(rv.c1, q1.x, acc[j][0]);
            acc[j][1] = fma2(rv.c1, q1.y, acc[j][1]);
            acc[j][0] = fma2(rv.c2, q2.x, acc[j][0]);
            acc[j][1] = fma2(rv.c2, q2.y, acc[j][1]);
            acc[j][0] = fma2(rv.c3, q3.x, acc[j][0]);
            acc[j][1] = fma2(rv.c3, q3.y, acc[j][1]);
        }
        if (t < NT - 1) w4[t & 3] = loadRow(col + (t + 4) * F_);
    }
}

__device__ __forceinline__ void store4(
    float4* __restrict__ o4, const u64 acc[U_][2])
{
#pragma unroll
    for (int j = 0; j < U_; ++j) {
        float2 lo = reinterpret_cast<const float2&>(acc[j][0]);
        float2 hi = reinterpret_cast<const float2&>(acc[j][1]);
        o4[(size_t)j * F_] = make_float4(lo.x, lo.y, hi.x, hi.y);
    }
}

__global__ __launch_bounds__(TPB, 3) void harm_conv_kernel(
    const float* __restrict__ x,
    float* __restrict__ out)
{
    extern __shared__ float4 tile[];              // [8][F_] rows s0-2 .. s0+5

    int bx = blockIdx.x;
    int sb = bx & (S_ / U_ - 1);
    int b  = bx >> 8;
    int s0 = sb * U_;
    int tid = threadIdx.x;

    const float4* __restrict__ xb =
        reinterpret_cast<const float4*>(x) + (size_t)b * S_ * F_;

    // ── stage 8 full rows (each thread: 2 cols x 8 rows), coalesced ──
    if (sb > 0 && sb < S_ / U_ - 1) {
        const float4* __restrict__ src = xb + (size_t)(s0 - 2) * F_ + tid;
#pragma unroll
        for (int i = 0; i < U_ + 4; ++i) {
            tile[i * F_ + tid]       = src[(size_t)i * F_];
            tile[i * F_ + tid + TPB] = src[(size_t)i * F_ + TPB];
        }
    } else {
#pragma unroll
        for (int i = 0; i < U_ + 4; ++i) {
            int sp = s0 + i - 2;
            if (sp >= 0 && sp < S_) {
                tile[i * F_ + tid]       = xb[(size_t)sp * F_ + tid];
                tile[i * F_ + tid + TPB] = xb[(size_t)sp * F_ + tid + TPB];
            } else {
                tile[i * F_ + tid]       = make_float4(0.f, 0.f, 0.f, 0.f);
                tile[i * F_ + tid + TPB] = make_float4(0.f, 0.f, 0.f, 0.f);
            }
        }
    }
    __syncthreads();

    float4* __restrict__ obase =
        reinterpret_cast<float4*>(out) + ((size_t)(b * S_ + s0)) * F_;

    // ── heavy chunk: f1 = tid (f < 256), literal-k harmonic stages ──
    int f1 = tid;
    {
        u64 acc[U_][2];
#pragma unroll
        for (int j = 0; j < U_; ++j) { acc[j][0] = 0ull; acc[j][1] = 0ull; }

        harmonic<0>(tile + f1, acc);              // k=0 always valid for f<256
        if (2 * f1 < F_) {                        // warp-coherent guards
            harmonic<1>(tile + 2 * f1, acc);
            if (3 * f1 < F_) {
                harmonic<2>(tile + 3 * f1, acc);
                if (4 * f1 < F_)
                    harmonic<3>(tile + 4 * f1, acc);
            }
        }
        store4(obase + f1, acc);
    }

    // ── light chunk: f2 = tid + 256 (f >= 256), k = 0 only ──
    int f2 = tid + TPB;
    {
        u64 acc[U_][2];
#pragma unroll
        for (int j = 0; j < U_; ++j) { acc[j][0] = 0ull; acc[j][1] = 0ull; }

        harmonic<0>(tile + f2, acc);
        store4(obase + f2, acc);
    }
}

extern "C" void kernel_launch(void* const* d_in, const int* in_sizes, int n_in,
                              void* d_out, int out_size)
{
    const float* x = (const float*)d_in[0];
    const float* W = (const float*)d_in[1];
    float* out = (float*)d_out;

    const int SMEM = (U_ + 4) * F_ * 16;          // 64 KB

    (void)cudaFuncSetAttribute(harm_conv_kernel,
                               cudaFuncAttributeMaxDynamicSharedMemorySize,
                               SMEM);

    // raw W layout IS the o-pair packed layout: direct copy, no transpose node
    cudaMemcpyToSymbolAsync(WcR, W, NT * NK * 16 * sizeof(float), 0,
                            cudaMemcpyDeviceToDevice, 0);

    int blocks = B_ * (S_ / U_);                  // 1024 uniform blocks
    harm_conv_kernel<<<blocks, TPB, SMEM>>>(x, out);
}

// round 17
// speedup vs baseline: 1.1068x; 1.1068x over previous
#include <cuda_runtime.h>

// out[b,s,f,o] = sum_{t,k,c} x[b, s+t-2, f*(k+1), c] * W[t,k,c,o],  f*(k+1) < F
// x [4,1024,512,4] f32, W [5,4,4,4] f32, out [4,1024,512,4] f32.
//
// R17: R13 core + phase overlap: each thread stages cols (tid, tid+256) and
//      computes light chunk + heavy k=0 DIRECTLY from the staged registers
//      before __syncthreads (no k=0 LDS round-trip, ~48% of fma moved under
//      staging latency). After BAR: only k=1..3 smem gathers.

#define B_  4
#define S_  1024
#define F_  512
#define U_  4
#define NT  5
#define NK  4
#define TPB 256

typedef unsigned long long u64;

// raw layout: WcR[t][k][c] = (W[t][k][c][0..1], W[t][k][c][2..3]) as o-pairs
__constant__ ulonglong2 WcR[NT][NK][4];

__device__ __forceinline__ u64 fma2(u64 a, u64 b, u64 c) {
    u64 d;
    asm("fma.rn.f32x2 %0, %1, %2, %3;" : "=l"(d) : "l"(a), "l"(b), "l"(c));
    return d;
}
__device__ __forceinline__ u64 dup2(float v) {
    u64 d;
    asm("mov.b64 %0, {%1, %1};" : "=l"(d) : "f"(v));
    return d;
}

struct Row { u64 c0, c1, c2, c3; };

__device__ __forceinline__ Row dupRow(float4 v) {
    Row r;
    r.c0 = dup2(v.x); r.c1 = dup2(v.y); r.c2 = dup2(v.z); r.c3 = dup2(v.w);
    return r;
}
__device__ __forceinline__ Row loadRow(const float4* __restrict__ p) {
    return dupRow(*p);
}

// core 5-tap x 4-output FFMA2 block for literal K, ring w4, reload callback
template <int K, typename RELOAD>
__device__ __forceinline__ void taps(Row w4[4], u64 acc[U_][2], RELOAD reload)
{
#pragma unroll
    for (int t = 0; t < NT; ++t) {
        ulonglong2 q0 = WcR[t][K][0];
        ulonglong2 q1 = WcR[t][K][1];
        ulonglong2 q2 = WcR[t][K][2];
        ulonglong2 q3 = WcR[t][K][3];
#pragma unroll
        for (int j = 0; j < U_; ++j) {
            Row rv = w4[(t + j) & 3];
            acc[j][0] = fma2(rv.c0, q0.x, acc[j][0]);
            acc[j][1] = fma2(rv.c0, q0.y, acc[j][1]);
            acc[j][0] = fma2(rv.c1, q1.x, acc[j][0]);
            acc[j][1] = fma2(rv.c1, q1.y, acc[j][1]);
            acc[j][0] = fma2(rv.c2, q2.x, acc[j][0]);
            acc[j][1] = fma2(rv.c2, q2.y, acc[j][1]);
            acc[j][0] = fma2(rv.c3, q3.x, acc[j][0]);
            acc[j][1] = fma2(rv.c3, q3.y, acc[j][1]);
        }
        if (t < NT - 1) w4[t & 3] = reload(t);
    }
}

// harmonic from smem column (k = 1..3, literal)
template <int K>
__device__ __forceinline__ void harmonic_smem(
    const float4* __restrict__ col, u64 acc[U_][2])
{
    Row w4[4];
#pragma unroll
    for (int m = 0; m < 4; ++m) w4[m] = loadRow(col + m * F_);
    taps<K>(w4, acc, [&](int t) { return loadRow(col + (t + 4) * F_); });
}

// harmonic k=0 from register-held rows
__device__ __forceinline__ void harmonic_reg(
    const float4 raw[U_ + 4], u64 acc[U_][2])
{
    Row w4[4];
#pragma unroll
    for (int m = 0; m < 4; ++m) w4[m] = dupRow(raw[m]);
    taps<0>(w4, acc, [&](int t) { return dupRow(raw[t + 4]); });
}

__device__ __forceinline__ void store4(
    float4* __restrict__ o4, const u64 acc[U_][2])
{
#pragma unroll
    for (int j = 0; j < U_; ++j) {
        float2 lo = reinterpret_cast<const float2&>(acc[j][0]);
        float2 hi = reinterpret_cast<const float2&>(acc[j][1]);
        o4[(size_t)j * F_] = make_float4(lo.x, lo.y, hi.x, hi.y);
    }
}

__global__ __launch_bounds__(TPB, 3) void harm_conv_kernel(
    const float* __restrict__ x,
    float* __restrict__ out)
{
    extern __shared__ float4 tile[];              // [8][F_] rows s0-2 .. s0+5

    int bx = blockIdx.x;
    int sb = bx & (S_ / U_ - 1);
    int b  = bx >> 8;
    int s0 = sb * U_;
    int tid = threadIdx.x;

    const float4* __restrict__ xb =
        reinterpret_cast<const float4*>(x) + (size_t)b * S_ * F_;
    float4* __restrict__ obase =
        reinterpret_cast<float4*>(out) + ((size_t)(b * S_ + s0)) * F_;

    bool interior = (sb > 0 && sb < S_ / U_ - 1);

    // ── light chunk: col f2 = tid+256. Stage + compute k=0 from regs ──
    int f2 = tid + TPB;
    {
        float4 raw[U_ + 4];
#pragma unroll
        for (int i = 0; i < U_ + 4; ++i) {
            int sp = s0 + i - 2;
            raw[i] = (interior || ((unsigned)sp < S_))
                   ? xb[(size_t)sp * F_ + f2]
                   : make_float4(0.f, 0.f, 0.f, 0.f);
        }
#pragma unroll
        for (int i = 0; i < U_ + 4; ++i)
            tile[i * F_ + f2] = raw[i];

        u64 accL[U_][2];
#pragma unroll
        for (int j = 0; j < U_; ++j) { accL[j][0] = 0ull; accL[j][1] = 0ull; }
        harmonic_reg(raw, accL);
        store4(obase + f2, accL);                 // light done, regs free
    }

    // ── heavy chunk: col f1 = tid. Stage + compute k=0 from regs ──
    int f1 = tid;
    u64 acc[U_][2];
#pragma unroll
    for (int j = 0; j < U_; ++j) { acc[j][0] = 0ull; acc[j][1] = 0ull; }
    {
        float4 raw[U_ + 4];
#pragma unroll
        for (int i = 0; i < U_ + 4; ++i) {
            int sp = s0 + i - 2;
            raw[i] = (interior || ((unsigned)sp < S_))
                   ? xb[(size_t)sp * F_ + f1]
                   : make_float4(0.f, 0.f, 0.f, 0.f);
        }
#pragma unroll
        for (int i = 0; i < U_ + 4; ++i)
            tile[i * F_ + f1] = raw[i];

        harmonic_reg(raw, acc);
    }

    __syncthreads();                              // tile ready for k >= 1

    // ── heavy k = 1..3 from smem (warp-coherent guards) ──
    if (2 * f1 < F_) {
        harmonic_smem<1>(tile + 2 * f1, acc);
        if (3 * f1 < F_) {
            harmonic_smem<2>(tile + 3 * f1, acc);
            if (4 * f1 < F_)
                harmonic_smem<3>(tile + 4 * f1, acc);
        }
    }
    store4(obase + f1, acc);
}

extern "C" void kernel_launch(void* const* d_in, const int* in_sizes, int n_in,
                              void* d_out, int out_size)
{
    const float* x = (const float*)d_in[0];
    const float* W = (const float*)d_in[1];
    float* out = (float*)d_out;

    const int SMEM = (U_ + 4) * F_ * 16;          // 64 KB

    (void)cudaFuncSetAttribute(harm_conv_kernel,
                               cudaFuncAttributeMaxDynamicSharedMemorySize,
                               SMEM);

    // raw W layout IS the o-pair packed layout: direct copy, no transpose node
    cudaMemcpyToSymbolAsync(WcR, W, NT * NK * 16 * sizeof(float), 0,
                            cudaMemcpyDeviceToDevice, 0);

    int blocks = B_ * (S_ / U_);                  // 1024 uniform blocks
    harm_conv_kernel<<<blocks, TPB, SMEM>>>(x, out);
}